// round 15
// baseline (speedup 1.0000x reference)
#include <cuda_runtime.h>
#include <cuda_fp16.h>
#include <cstdint>

#define N_NODES 100000
#define N_EDGES 1600000
#define M_PAD   100096   // 782 * 128
#define IN_CH   128
#define HID_CH  256
#define OUT_CH  128
#define SCAN_BLOCKS 98   // 98 * 1024 >= N_NODES
#define TR_BLOCKS   192  // transpose tiles for all 4 weights

// ---------------- static scratch (no allocation allowed) ----------------
__device__ int    g_cnt[N_NODES];          // zero-init; re-zeroed by scan2 each call
__device__ int    g_bsum[SCAN_BLOCKS];
__device__ int    g_rowptr[N_NODES + 1];
__device__ int    g_fill[N_NODES];
__device__ int    g_srcs[N_EDGES];
__device__ __half g_xh[(size_t)N_NODES * IN_CH];          // fp16 copy of x
__device__ __half g_wt[196608];                           // 4 transposed fp16 weights
__device__ __half g_bufA[(size_t)M_PAD * HID_CH];
__device__ __half g_h   [(size_t)M_PAD * HID_CH];

// ---------------- PTX helpers (compute_103-safe: sm_80-era features only) ----
__device__ __forceinline__ uint32_t smem_u32(const void* p) {
    uint32_t a;
    asm("{ .reg .u64 t; cvta.to.shared.u64 t, %1; cvt.u32.u64 %0, t; }" : "=r"(a) : "l"(p));
    return a;
}
#define CP_ASYNC16(s, g) \
    asm volatile("cp.async.cg.shared.global [%0], [%1], 16;" :: "r"(s), "l"(g))
#define CP_COMMIT()  asm volatile("cp.async.commit_group;" ::: "memory")
#define CP_WAIT(n)   asm volatile("cp.async.wait_group %0;" :: "n"(n) : "memory")

__device__ __forceinline__ void ldsm4(uint32_t* r, uint32_t addr) {
    asm volatile("ldmatrix.sync.aligned.m8n8.x4.shared.b16 {%0,%1,%2,%3}, [%4];"
                 : "=r"(r[0]), "=r"(r[1]), "=r"(r[2]), "=r"(r[3]) : "r"(addr));
}
__device__ __forceinline__ void mma16816(float* c, const uint32_t* a, const uint32_t* b) {
    asm volatile("mma.sync.aligned.m16n8k16.row.col.f32.f16.f16.f32 "
                 "{%0,%1,%2,%3}, {%4,%5,%6,%7}, {%8,%9}, {%0,%1,%2,%3};"
                 : "+f"(c[0]), "+f"(c[1]), "+f"(c[2]), "+f"(c[3])
                 : "r"(a[0]), "r"(a[1]), "r"(a[2]), "r"(a[3]), "r"(b[0]), "r"(b[1]));
}

// ---------------- CSR build: hist (8 edges/thread) + x->fp16 convert ----------------
__global__ void hist_cvt_kernel(const int* __restrict__ edge_index,
                                const float* __restrict__ x) {
    const int i = blockIdx.x * blockDim.x + threadIdx.x;
    const int nthreads = gridDim.x * blockDim.x;
    int e0 = i * 8;
    if (e0 + 7 < N_EDGES) {
        int4 d0 = *(const int4*)(edge_index + N_EDGES + e0);
        int4 d1 = *(const int4*)(edge_index + N_EDGES + e0 + 4);
        atomicAdd(&g_cnt[d0.x], 1);
        atomicAdd(&g_cnt[d0.y], 1);
        atomicAdd(&g_cnt[d0.z], 1);
        atomicAdd(&g_cnt[d0.w], 1);
        atomicAdd(&g_cnt[d1.x], 1);
        atomicAdd(&g_cnt[d1.y], 1);
        atomicAdd(&g_cnt[d1.z], 1);
        atomicAdd(&g_cnt[d1.w], 1);
    } else {
        for (int e = e0; e < N_EDGES; e++) atomicAdd(&g_cnt[edge_index[N_EDGES + e]], 1);
    }
    // x -> fp16: grid-stride over 6.4M half2
    for (int idx = i; idx < N_NODES * IN_CH / 2; idx += nthreads) {
        float2 v = ((const float2*)x)[idx];
        ((__half2*)g_xh)[idx] = __floats2half2_rn(v.x, v.y);
    }
}

// scan phase 1 + weight transpose, merged heterogeneous launch
__global__ void scan1_tr_kernel(const float* __restrict__ W1a, const float* __restrict__ W1b,
                                const float* __restrict__ W2a, const float* __restrict__ W2b,
                                __half* __restrict__ wt) {
    __shared__ float sh[32 * 33];
    const int tid = threadIdx.x;

    if (blockIdx.x >= SCAN_BLOCKS) {
        int b = blockIdx.x - SCAN_BLOCKS;
        const float* W; __half* Wt; int K, N, tx;
        if (b < 32)       { W = W1a; Wt = wt;          K = 128; N = 256; tx = b; }
        else if (b < 96)  { W = W1b; Wt = wt + 32768;  K = 256; N = 256; tx = b - 32; }
        else if (b < 160) { W = W2a; Wt = wt + 98304;  K = 256; N = 256; tx = b - 96; }
        else              { W = W2b; Wt = wt + 163840; K = 256; N = 128; tx = b - 160; }
        const int nt = N / 32;
        const int bx = (tx % nt) * 32;
        const int by = (tx / nt) * 32;
        const int lx = tid & 31, ly = tid >> 5;
        sh[ly * 33 + lx] = W[(size_t)(by + ly) * N + bx + lx];
        __syncthreads();
        Wt[(size_t)(bx + ly) * K + by + lx] = __float2half(sh[lx * 33 + ly]);
        return;
    }

    int* wtot = (int*)sh;
    const int b = blockIdx.x;
    const int idx = b * 1024 + tid;
    int v = (idx < N_NODES) ? g_cnt[idx] : 0;
    const int lane = tid & 31, w = tid >> 5;
    int inc = v;
#pragma unroll
    for (int d = 1; d < 32; d <<= 1) {
        int t = __shfl_up_sync(0xFFFFFFFF, inc, d);
        if (lane >= d) inc += t;
    }
    if (lane == 31) wtot[w] = inc;
    __syncthreads();
    if (w == 0) {
        int t = wtot[lane];
#pragma unroll
        for (int d = 1; d < 32; d <<= 1) {
            int u = __shfl_up_sync(0xFFFFFFFF, t, d);
            if (lane >= d) t += u;
        }
        wtot[lane] = t;
    }
    __syncthreads();
    int ex = inc - v + (w > 0 ? wtot[w - 1] : 0);
    if (idx < N_NODES) g_rowptr[idx] = ex;
    if (tid == 0) g_bsum[b] = wtot[31];
}

// scan phase 2: parallel block-offset scan; emit rowptr/fill; zero cnt
__global__ void scan2_kernel() {
    __shared__ int sb[128];
    const int b = blockIdx.x, tid = threadIdx.x;
    if (tid < 128) sb[tid] = (tid < SCAN_BLOCKS) ? g_bsum[tid] : 0;
    __syncthreads();
#pragma unroll
    for (int off = 1; off < 128; off <<= 1) {
        int v = 0;
        if (tid < 128 && tid >= off) v = sb[tid - off];
        __syncthreads();
        if (tid < 128) sb[tid] += v;
        __syncthreads();
    }
    const int s_off = (b == 0) ? 0 : sb[b - 1];
    if (tid == 0 && b == SCAN_BLOCKS - 1) g_rowptr[N_NODES] = sb[SCAN_BLOCKS - 1];
    const int idx = b * 1024 + tid;
    if (idx < N_NODES) {
        int r = g_rowptr[idx] + s_off;
        g_rowptr[idx] = r;
        g_fill[idx]   = r;
        g_cnt[idx]    = 0;
    }
}

// scatter: 8 edges/thread, batched int4 loads, 8 atomics in flight
__global__ void scatter_kernel(const int* __restrict__ edge_index) {
    int i = blockIdx.x * blockDim.x + threadIdx.x;
    int e0 = i * 8;
    if (e0 + 7 < N_EDGES) {
        int4 s0 = *(const int4*)(edge_index + e0);
        int4 s1 = *(const int4*)(edge_index + e0 + 4);
        int4 d0 = *(const int4*)(edge_index + N_EDGES + e0);
        int4 d1 = *(const int4*)(edge_index + N_EDGES + e0 + 4);
        int p0 = atomicAdd(&g_fill[d0.x], 1);
        int p1 = atomicAdd(&g_fill[d0.y], 1);
        int p2 = atomicAdd(&g_fill[d0.z], 1);
        int p3 = atomicAdd(&g_fill[d0.w], 1);
        int p4 = atomicAdd(&g_fill[d1.x], 1);
        int p5 = atomicAdd(&g_fill[d1.y], 1);
        int p6 = atomicAdd(&g_fill[d1.z], 1);
        int p7 = atomicAdd(&g_fill[d1.w], 1);
        g_srcs[p0] = s0.x;
        g_srcs[p1] = s0.y;
        g_srcs[p2] = s0.z;
        g_srcs[p3] = s0.w;
        g_srcs[p4] = s1.x;
        g_srcs[p5] = s1.y;
        g_srcs[p6] = s1.z;
        g_srcs[p7] = s1.w;
    } else {
        for (int e = e0; e < N_EDGES; e++) {
            int dst = edge_index[N_EDGES + e];
            int pos = atomicAdd(&g_fill[dst], 1);
            g_srcs[pos] = edge_index[e];
        }
    }
}

// ------- aggregation CH=128 (R7-proven) -------
__global__ void agg128_kernel(const __half* __restrict__ X,
                              const float* __restrict__ eps_ptr,
                              __half* __restrict__ OUT) {
    int gw   = (blockIdx.x * blockDim.x + threadIdx.x) >> 5;
    int lane = threadIdx.x & 31;
    if (gw >= M_PAD) return;
    const bool hi = lane >= 16;
    const int  l4 = lane & 15;
    uint4* orow = (uint4*)(OUT + (size_t)gw * 128);

    if (gw >= N_NODES) {
        if (!hi) orow[l4] = make_uint4(0u, 0u, 0u, 0u);
        return;
    }

    float2 acc[4];
    if (!hi) {
        const float scale = 1.0f + __ldg(eps_ptr);
        uint4 u = __ldg((const uint4*)(X + (size_t)gw * 128) + l4);
        const __half2* hh = (const __half2*)&u;
#pragma unroll
        for (int k = 0; k < 4; k++) {
            float2 f = __half22float2(hh[k]);
            acc[k] = make_float2(f.x * scale, f.y * scale);
        }
    } else {
#pragma unroll
        for (int k = 0; k < 4; k++) acc[k] = make_float2(0.f, 0.f);
    }

    const int beg = g_rowptr[gw];
    const int end = g_rowptr[gw + 1];
    const int sel = hi ? 1 : 0;
    int j = beg;
    for (; j + 3 < end; j += 4) {
        int sA = __ldg(&g_srcs[j + sel]);
        int sB = __ldg(&g_srcs[j + 2 + sel]);
        uint4 uA = __ldg((const uint4*)(X + (size_t)sA * 128) + l4);
        uint4 uB = __ldg((const uint4*)(X + (size_t)sB * 128) + l4);
        const __half2* hA = (const __half2*)&uA;
        const __half2* hB = (const __half2*)&uB;
#pragma unroll
        for (int k = 0; k < 4; k++) {
            float2 f = __half22float2(__hadd2(hA[k], hB[k]));
            acc[k].x += f.x; acc[k].y += f.y;
        }
    }
    if (j + 1 < end) {
        int s = __ldg(&g_srcs[j + sel]);
        uint4 u = __ldg((const uint4*)(X + (size_t)s * 128) + l4);
        const __half2* hh = (const __half2*)&u;
#pragma unroll
        for (int k = 0; k < 4; k++) {
            float2 f = __half22float2(hh[k]);
            acc[k].x += f.x; acc[k].y += f.y;
        }
        j += 2;
    }
    if (j < end && !hi) {
        int s = __ldg(&g_srcs[j]);
        uint4 u = __ldg((const uint4*)(X + (size_t)s * 128) + l4);
        const __half2* hh = (const __half2*)&u;
#pragma unroll
        for (int k = 0; k < 4; k++) {
            float2 f = __half22float2(hh[k]);
            acc[k].x += f.x; acc[k].y += f.y;
        }
    }

#pragma unroll
    for (int k = 0; k < 4; k++) {
        acc[k].x += __shfl_down_sync(0xFFFFFFFF, acc[k].x, 16);
        acc[k].y += __shfl_down_sync(0xFFFFFFFF, acc[k].y, 16);
    }
    if (!hi) {
        uint4 o;
        __half2* oh = (__half2*)&o;
#pragma unroll
        for (int k = 0; k < 4; k++) oh[k] = __floats2half2_rn(acc[k].x, acc[k].y);
        orow[l4] = o;
    }
}

// ------- aggregation CH=256: software-pipelined index loads -------
__global__ void agg256_kernel(const __half* __restrict__ X,
                              const float* __restrict__ eps_ptr,
                              __half* __restrict__ OUT) {
    int gw   = (blockIdx.x * blockDim.x + threadIdx.x) >> 5;
    int lane = threadIdx.x & 31;
    if (gw >= M_PAD) return;

    __half2* orow = (__half2*)(OUT + (size_t)gw * 256) + lane * 4;
    if (gw >= N_NODES) {
        __half2 z = __floats2half2_rn(0.f, 0.f);
#pragma unroll
        for (int v = 0; v < 4; v++) orow[v] = z;
        return;
    }

    const float scale = 1.0f + __ldg(eps_ptr);
    float2 acc[4];
    {
        uint4 u = __ldg((const uint4*)(X + (size_t)gw * 256) + lane);
        const __half2* hh = (const __half2*)&u;
#pragma unroll
        for (int v = 0; v < 4; v++) {
            float2 f = __half22float2(hh[v]);
            acc[v] = make_float2(f.x * scale, f.y * scale);
        }
    }

    const int beg = g_rowptr[gw];
    const int end = g_rowptr[gw + 1];
    int j = beg;

    // pipelined quad loop: prefetch next indices before consuming current rows
    int i0, i1, i2, i3;
    if (j + 3 < end) {
        i0 = __ldg(&g_srcs[j + 0]);
        i1 = __ldg(&g_srcs[j + 1]);
        i2 = __ldg(&g_srcs[j + 2]);
        i3 = __ldg(&g_srcs[j + 3]);
    }
    for (; j + 3 < end; ) {
        const int jn = j + 4;
        int n0, n1, n2, n3;
        if (jn + 3 < end) {
            n0 = __ldg(&g_srcs[jn + 0]);
            n1 = __ldg(&g_srcs[jn + 1]);
            n2 = __ldg(&g_srcs[jn + 2]);
            n3 = __ldg(&g_srcs[jn + 3]);
        }
        uint4 u0 = __ldg((const uint4*)(X + (size_t)i0 * 256) + lane);
        uint4 u1 = __ldg((const uint4*)(X + (size_t)i1 * 256) + lane);
        uint4 u2 = __ldg((const uint4*)(X + (size_t)i2 * 256) + lane);
        uint4 u3 = __ldg((const uint4*)(X + (size_t)i3 * 256) + lane);
        const __half2* h0 = (const __half2*)&u0;
        const __half2* h1 = (const __half2*)&u1;
        const __half2* h2 = (const __half2*)&u2;
        const __half2* h3 = (const __half2*)&u3;
#pragma unroll
        for (int v = 0; v < 4; v++) {
            float2 f0 = __half22float2(__hadd2(h0[v], h1[v]));
            float2 f1 = __half22float2(__hadd2(h2[v], h3[v]));
            acc[v].x += f0.x + f1.x;
            acc[v].y += f0.y + f1.y;
        }
        j = jn;
        i0 = n0; i1 = n1; i2 = n2; i3 = n3;
    }
    if (j + 1 < end) {
        uint4 u0 = __ldg((const uint4*)(X + (size_t)__ldg(&g_srcs[j + 0]) * 256) + lane);
        uint4 u1 = __ldg((const uint4*)(X + (size_t)__ldg(&g_srcs[j + 1]) * 256) + lane);
        const __half2* h0 = (const __half2*)&u0;
        const __half2* h1 = (const __half2*)&u1;
#pragma unroll
        for (int v = 0; v < 4; v++) {
            float2 f0 = __half22float2(__hadd2(h0[v], h1[v]));
            acc[v].x += f0.x; acc[v].y += f0.y;
        }
        j += 2;
    }
    if (j < end) {
        uint4 u0 = __ldg((const uint4*)(X + (size_t)__ldg(&g_srcs[j]) * 256) + lane);
        const __half2* h0 = (const __half2*)&u0;
#pragma unroll
        for (int v = 0; v < 4; v++) {
            float2 f0 = __half22float2(h0[v]);
            acc[v].x += f0.x; acc[v].y += f0.y;
        }
    }

#pragma unroll
    for (int v = 0; v < 4; v++) orow[v] = __floats2half2_rn(acc[v].x, acc[v].y);
}

// ------- fused 2-GEMM MLP (R8/R11-proven): out = actB(relu(A@WaT + ba) @ WbT + bb) -------
template <int K1, int N2, bool OUT_HALF>
__global__ void __launch_bounds__(512, 1)
fused_mlp(const __half* __restrict__ A, const __half* __restrict__ WtA,
          const float* __restrict__ biasA, const __half* __restrict__ WtB,
          const float* __restrict__ biasB, void* __restrict__ outv) {
    constexpr int PITCH  = 80;
    constexpr int A_STG  = 128 * PITCH;          // 10240
    constexpr int B_STG  = 256 * PITCH;          // 20480
    constexpr int STG    = A_STG + B_STG;        // 30720
    constexpr int MID_OFF = 3 * STG;             // 92160
    constexpr int NF2    = N2 / 32;
    extern __shared__ __align__(128) char smem[];
    const uint32_t sbase = smem_u32(smem);

    const int tid  = threadIdx.x;
    const int lane = tid & 31;
    const int wid  = tid >> 5;
    const int wm   = wid & 3;
    const int wn   = wid >> 2;
    const size_t brow = (size_t)blockIdx.x * 128;

    const int g  = lane >> 3;
    const int l7 = lane & 7;
    const uint32_t aRel   = (uint32_t)(wm * 32 + (g & 1) * 8 + l7) * PITCH + (g >> 1) * 16;
    const uint32_t bRelA  = (uint32_t)(wn * 64 + ((g >> 1) & 1) * 8 + l7) * PITCH + (g & 1) * 16;
    const uint32_t bRelB  = (uint32_t)(wn * (N2 / 4) + ((g >> 1) & 1) * 8 + l7) * PITCH + (g & 1) * 16;
    const int lr = lane >> 2;
    const int lc = (lane & 3) * 2;

    float c[2][8][4];
#pragma unroll
    for (int mf = 0; mf < 2; mf++)
#pragma unroll
        for (int nf = 0; nf < 8; nf++)
#pragma unroll
            for (int e = 0; e < 4; e++) c[mf][nf][e] = 0.0f;

    auto load_stageA = [&](int t, int buf) {
        const uint32_t sb = sbase + (uint32_t)buf * STG;
        {
            int row = tid >> 2, cc = tid & 3;
            CP_ASYNC16(sb + row * PITCH + cc * 16, A + (brow + row) * K1 + t * 32 + cc * 8);
        }
#pragma unroll
        for (int p = 1; p < 3; p++) {
            int i2 = tid + p * 512 - 512;
            int row = i2 >> 2, cc = i2 & 3;
            CP_ASYNC16(sb + A_STG + row * PITCH + cc * 16,
                       WtA + (size_t)row * K1 + t * 32 + cc * 8);
        }
    };
    auto load_stageB = [&](int t, int buf) {
        const uint32_t sb = sbase + (uint32_t)buf * STG + A_STG;
#pragma unroll
        for (int p = 0; p < (N2 * 4) / 512; p++) {
            int idx = tid + p * 512;
            int row = idx >> 2, cc = idx & 3;
            CP_ASYNC16(sb + row * PITCH + cc * 16,
                       WtB + (size_t)row * 256 + t * 32 + cc * 8);
        }
    };

    // ================= phase A mainloop =================
    constexpr int T1 = K1 / 32;
    load_stageA(0, 0); CP_COMMIT();
    load_stageA(1, 1); CP_COMMIT();
    int buf = 0;
    for (int t = 0; t < T1; t++) {
        CP_WAIT(1);
        __syncthreads();
        if (t + 2 < T1) load_stageA(t + 2, (t + 2) % 3);
        CP_COMMIT();
        const uint32_t soff = (uint32_t)buf * STG;
#pragma unroll
        for (int ks = 0; ks < 2; ks++) {
            uint32_t a[2][4], b[8][2];
            ldsm4(a[0], sbase + soff + aRel + ks * 32);
            ldsm4(a[1], sbase + soff + aRel + 16 * PITCH + ks * 32);
#pragma unroll
            for (int p = 0; p < 4; p++) {
                uint32_t r[4];
                ldsm4(r, sbase + soff + A_STG + bRelA + p * 16 * PITCH + ks * 32);
                b[2 * p][0] = r[0]; b[2 * p][1] = r[1];
                b[2 * p + 1][0] = r[2]; b[2 * p + 1][1] = r[3];
            }
#pragma unroll
            for (int mf = 0; mf < 2; mf++)
#pragma unroll
                for (int nf = 0; nf < 8; nf++)
                    mma16816(c[mf][nf], a[mf], b[nf]);
        }
        buf = (buf == 2) ? 0 : buf + 1;
    }
    __syncthreads();

    // prefetch phase-B stages while epilogue A runs
    load_stageB(0, 0); CP_COMMIT();
    load_stageB(1, 1); CP_COMMIT();

    // ---- phase A epilogue -> mid tile in SMEM (fp16, slab layout) ----
#pragma unroll
    for (int nf = 0; nf < 8; nf++) {
        const int col0 = wn * 64 + nf * 8 + lc;
        float2 bv = *(const float2*)(biasA + col0);
        const int slab = col0 >> 5, cin = col0 & 31;
        const uint32_t mb = sbase + MID_OFF + slab * A_STG + cin * 2;
#pragma unroll
        for (int mf = 0; mf < 2; mf++) {
            const int row0 = wm * 32 + mf * 16 + lr;
            float v0 = fmaxf(c[mf][nf][0] + bv.x, 0.f);
            float v1 = fmaxf(c[mf][nf][1] + bv.y, 0.f);
            float v2 = fmaxf(c[mf][nf][2] + bv.x, 0.f);
            float v3 = fmaxf(c[mf][nf][3] + bv.y, 0.f);
            __half2 h0 = __floats2half2_rn(v0, v1);
            __half2 h1 = __floats2half2_rn(v2, v3);
            asm volatile("st.shared.b32 [%0], %1;" :: "r"(mb + row0 * PITCH), "r"(*(uint32_t*)&h0));
            asm volatile("st.shared.b32 [%0], %1;" :: "r"(mb + (row0 + 8) * PITCH), "r"(*(uint32_t*)&h1));
        }
    }
#pragma unroll
    for (int mf = 0; mf < 2; mf++)
#pragma unroll
        for (int nf = 0; nf < 8; nf++)
#pragma unroll
            for (int e = 0; e < 4; e++) c[mf][nf][e] = 0.0f;
    __syncthreads();

    // ================= phase B mainloop (K2 = 256) =================
    buf = 0;
    for (int t = 0; t < 8; t++) {
        CP_WAIT(1);
        __syncthreads();
        if (t + 2 < 8) load_stageB(t + 2, (t + 2) % 3);
        CP_COMMIT();
        const uint32_t soff = (uint32_t)buf * STG + A_STG;
        const uint32_t amid = sbase + MID_OFF + (uint32_t)t * A_STG;
#pragma unroll
        for (int ks = 0; ks < 2; ks++) {
            uint32_t a[2][4], b[8][2];
            ldsm4(a[0], amid + aRel + ks * 32);
            ldsm4(a[1], amid + aRel + 16 * PITCH + ks * 32);
#pragma unroll
            for (int p = 0; p < NF2 / 2; p++) {
                uint32_t r[4];
                ldsm4(r, sbase + soff + bRelB + p * 16 * PITCH + ks * 32);
                b[2 * p][0] = r[0]; b[2 * p][1] = r[1];
                b[2 * p + 1][0] = r[2]; b[2 * p + 1][1] = r[3];
            }
#pragma unroll
            for (int mf = 0; mf < 2; mf++)
#pragma unroll
                for (int nf = 0; nf < NF2; nf++)
                    mma16816(c[mf][nf], a[mf], b[nf]);
        }
        buf = (buf == 2) ? 0 : buf + 1;
    }

    // ---- phase B epilogue ----
#pragma unroll
    for (int nf = 0; nf < NF2; nf++) {
        const int col = wn * (N2 / 4) + nf * 8 + lc;
        float2 bv = *(const float2*)(biasB + col);
#pragma unroll
        for (int mf = 0; mf < 2; mf++) {
            size_t r0 = brow + wm * 32 + mf * 16 + lr;
            float v0 = c[mf][nf][0] + bv.x, v1 = c[mf][nf][1] + bv.y;
            float v2 = c[mf][nf][2] + bv.x, v3 = c[mf][nf][3] + bv.y;
            if (OUT_HALF) {
                v0 = fmaxf(v0, 0.f); v1 = fmaxf(v1, 0.f);
                v2 = fmaxf(v2, 0.f); v3 = fmaxf(v3, 0.f);
                __half* C = (__half*)outv;
                *(__half2*)(C + r0 * N2 + col)       = __floats2half2_rn(v0, v1);
                *(__half2*)(C + (r0 + 8) * N2 + col) = __floats2half2_rn(v2, v3);
            } else {
                float* C = (float*)outv;
                if (r0 < N_NODES)     *(float2*)(C + r0 * N2 + col)       = make_float2(v0, v1);
                if (r0 + 8 < N_NODES) *(float2*)(C + (r0 + 8) * N2 + col) = make_float2(v2, v3);
            }
        }
    }
}

// ---------------- launch ----------------
extern "C" void kernel_launch(void* const* d_in, const int* in_sizes, int n_in,
                              void* d_out, int out_size) {
    const float* x    = (const float*)d_in[0];
    const int*   ei   = (const int*)  d_in[1];
    const float* eps1 = (const float*)d_in[2];
    const float* W1a  = (const float*)d_in[3];
    const float* b1a  = (const float*)d_in[4];
    const float* W1b  = (const float*)d_in[5];
    const float* b1b  = (const float*)d_in[6];
    const float* eps2 = (const float*)d_in[7];
    const float* W2a  = (const float*)d_in[8];
    const float* b2a  = (const float*)d_in[9];
    const float* W2b  = (const float*)d_in[10];
    const float* b2b  = (const float*)d_in[11];
    float* out = (float*)d_out;

    __half *xh, *bufA, *h, *wt;
    cudaGetSymbolAddress((void**)&xh,   g_xh);
    cudaGetSymbolAddress((void**)&bufA, g_bufA);
    cudaGetSymbolAddress((void**)&h,    g_h);
    cudaGetSymbolAddress((void**)&wt,   g_wt);
    __half* wt1a = wt;               // [256][128]
    __half* wt1b = wt + 32768;       // [256][256]
    __half* wt2a = wt + 98304;       // [256][256]
    __half* wt2b = wt + 163840;      // [128][256]

    constexpr int SMEM_MLP = 3 * 30720 + 8 * 10240;   // 174080
    cudaFuncSetAttribute((const void*)fused_mlp<128, 256, true>,
                         cudaFuncAttributeMaxDynamicSharedMemorySize, SMEM_MLP);
    cudaFuncSetAttribute((const void*)fused_mlp<256, 128, false>,
                         cudaFuncAttributeMaxDynamicSharedMemorySize, SMEM_MLP);

    const int agg_blocks = (M_PAD * 32 + 255) / 256;
    const int G = M_PAD / 128;  // 782

    hist_cvt_kernel<<<(N_EDGES / 8 + 255) / 256, 256>>>(ei, x);                  // 1
    scan1_tr_kernel<<<SCAN_BLOCKS + TR_BLOCKS, 1024>>>(W1a, W1b, W2a, W2b, wt);  // 2
    scan2_kernel<<<SCAN_BLOCKS, 1024>>>();                                       // 3
    scatter_kernel<<<(N_EDGES / 8 + 255) / 256, 256>>>(ei);                      // 4 (profiled)

    // ---- layer 1 ----
    agg128_kernel<<<agg_blocks, 256>>>(xh, eps1, bufA);                          // 5
    fused_mlp<128, 256, true><<<G, 512, SMEM_MLP>>>(bufA, wt1a, b1a, wt1b, b1b, h);

    // ---- layer 2 ----
    agg256_kernel<<<agg_blocks, 256>>>(h, eps2, bufA);
    fused_mlp<256, 128, false><<<G, 512, SMEM_MLP>>>(bufA, wt2a, b2a, wt2b, b2b, out);
}

// round 16
// speedup vs baseline: 1.0262x; 1.0262x over previous
#include <cuda_runtime.h>
#include <cuda_fp16.h>
#include <cstdint>

#define N_NODES 100000
#define N_EDGES 1600000
#define M_PAD   100096   // 782 * 128
#define IN_CH   128
#define HID_CH  256
#define OUT_CH  128
#define SCAN_BLOCKS 98   // 98 * 1024 >= N_NODES
#define TR_BLOCKS   192  // transpose tiles for all 4 weights

// ---------------- static scratch (no allocation allowed) ----------------
__device__ int    g_cnt[N_NODES];          // zero-init; re-zeroed by scan2 each call
__device__ int    g_bsum[SCAN_BLOCKS];
__device__ int    g_rowptr[N_NODES + 1];
__device__ int    g_fill[N_NODES];
__device__ int    g_srcs[N_EDGES];
__device__ __half g_xh[(size_t)N_NODES * IN_CH];          // fp16 copy of x
__device__ __half g_wt[196608];                           // 4 transposed fp16 weights
__device__ __half g_bufA[(size_t)M_PAD * HID_CH];
__device__ __half g_h   [(size_t)M_PAD * HID_CH];

// ---------------- PTX helpers (compute_103-safe: sm_80-era features only) ----
__device__ __forceinline__ uint32_t smem_u32(const void* p) {
    uint32_t a;
    asm("{ .reg .u64 t; cvta.to.shared.u64 t, %1; cvt.u32.u64 %0, t; }" : "=r"(a) : "l"(p));
    return a;
}
#define CP_ASYNC16(s, g) \
    asm volatile("cp.async.cg.shared.global [%0], [%1], 16;" :: "r"(s), "l"(g))
#define CP_COMMIT()  asm volatile("cp.async.commit_group;" ::: "memory")
#define CP_WAIT(n)   asm volatile("cp.async.wait_group %0;" :: "n"(n) : "memory")

__device__ __forceinline__ void ldsm4(uint32_t* r, uint32_t addr) {
    asm volatile("ldmatrix.sync.aligned.m8n8.x4.shared.b16 {%0,%1,%2,%3}, [%4];"
                 : "=r"(r[0]), "=r"(r[1]), "=r"(r[2]), "=r"(r[3]) : "r"(addr));
}
__device__ __forceinline__ void mma16816(float* c, const uint32_t* a, const uint32_t* b) {
    asm volatile("mma.sync.aligned.m16n8k16.row.col.f32.f16.f16.f32 "
                 "{%0,%1,%2,%3}, {%4,%5,%6,%7}, {%8,%9}, {%0,%1,%2,%3};"
                 : "+f"(c[0]), "+f"(c[1]), "+f"(c[2]), "+f"(c[3])
                 : "r"(a[0]), "r"(a[1]), "r"(a[2]), "r"(a[3]), "r"(b[0]), "r"(b[1]));
}

// ---------------- CSR build: hist (4 edges/thread, batched loads) + cvt ----------------
__global__ void hist_cvt_kernel(const int* __restrict__ edge_index,
                                const float* __restrict__ x) {
    int i = blockIdx.x * blockDim.x + threadIdx.x;
    int e0 = i * 4;
    if (e0 + 3 < N_EDGES) {
        int4 d = *(const int4*)(edge_index + N_EDGES + e0);   // 16B coalesced dst load
        atomicAdd(&g_cnt[d.x], 1);
        atomicAdd(&g_cnt[d.y], 1);
        atomicAdd(&g_cnt[d.z], 1);
        atomicAdd(&g_cnt[d.w], 1);
    } else {
        for (int e = e0; e < N_EDGES; e++) atomicAdd(&g_cnt[edge_index[N_EDGES + e]], 1);
    }
    // x -> fp16 (16 half2 per thread to cover 6.4M halfs with 400k threads)
#pragma unroll
    for (int p = 0; p < 16; p++) {
        int idx = i + p * 400000;
        if (idx < N_NODES * IN_CH / 2) {
            float2 v = ((const float2*)x)[idx];
            ((__half2*)g_xh)[idx] = __floats2half2_rn(v.x, v.y);
        }
    }
}

// scan phase 1 + weight transpose, merged heterogeneous launch
__global__ void scan1_tr_kernel(const float* __restrict__ W1a, const float* __restrict__ W1b,
                                const float* __restrict__ W2a, const float* __restrict__ W2b,
                                __half* __restrict__ wt) {
    __shared__ float sh[32 * 33];
    const int tid = threadIdx.x;

    if (blockIdx.x >= SCAN_BLOCKS) {
        int b = blockIdx.x - SCAN_BLOCKS;
        const float* W; __half* Wt; int K, N, tx;
        if (b < 32)       { W = W1a; Wt = wt;          K = 128; N = 256; tx = b; }
        else if (b < 96)  { W = W1b; Wt = wt + 32768;  K = 256; N = 256; tx = b - 32; }
        else if (b < 160) { W = W2a; Wt = wt + 98304;  K = 256; N = 256; tx = b - 96; }
        else              { W = W2b; Wt = wt + 163840; K = 256; N = 128; tx = b - 160; }
        const int nt = N / 32;
        const int bx = (tx % nt) * 32;
        const int by = (tx / nt) * 32;
        const int lx = tid & 31, ly = tid >> 5;
        sh[ly * 33 + lx] = W[(size_t)(by + ly) * N + bx + lx];
        __syncthreads();
        Wt[(size_t)(bx + ly) * K + by + lx] = __float2half(sh[lx * 33 + ly]);
        return;
    }

    int* wtot = (int*)sh;
    const int b = blockIdx.x;
    const int idx = b * 1024 + tid;
    int v = (idx < N_NODES) ? g_cnt[idx] : 0;
    const int lane = tid & 31, w = tid >> 5;
    int inc = v;
#pragma unroll
    for (int d = 1; d < 32; d <<= 1) {
        int t = __shfl_up_sync(0xFFFFFFFF, inc, d);
        if (lane >= d) inc += t;
    }
    if (lane == 31) wtot[w] = inc;
    __syncthreads();
    if (w == 0) {
        int t = wtot[lane];
#pragma unroll
        for (int d = 1; d < 32; d <<= 1) {
            int u = __shfl_up_sync(0xFFFFFFFF, t, d);
            if (lane >= d) t += u;
        }
        wtot[lane] = t;
    }
    __syncthreads();
    int ex = inc - v + (w > 0 ? wtot[w - 1] : 0);
    if (idx < N_NODES) g_rowptr[idx] = ex;
    if (tid == 0) g_bsum[b] = wtot[31];
}

// scan phase 2: parallel block-offset scan; emit rowptr/fill; zero cnt
__global__ void scan2_kernel() {
    __shared__ int sb[128];
    const int b = blockIdx.x, tid = threadIdx.x;
    if (tid < 128) sb[tid] = (tid < SCAN_BLOCKS) ? g_bsum[tid] : 0;
    __syncthreads();
#pragma unroll
    for (int off = 1; off < 128; off <<= 1) {
        int v = 0;
        if (tid < 128 && tid >= off) v = sb[tid - off];
        __syncthreads();
        if (tid < 128) sb[tid] += v;
        __syncthreads();
    }
    const int s_off = (b == 0) ? 0 : sb[b - 1];
    if (tid == 0 && b == SCAN_BLOCKS - 1) g_rowptr[N_NODES] = sb[SCAN_BLOCKS - 1];
    const int idx = b * 1024 + tid;
    if (idx < N_NODES) {
        int r = g_rowptr[idx] + s_off;
        g_rowptr[idx] = r;
        g_fill[idx]   = r;
        g_cnt[idx]    = 0;
    }
}

// scatter: 4 edges/thread, batched int4 loads, 4 atomics in flight (R14-proven)
__global__ void scatter_kernel(const int* __restrict__ edge_index) {
    int i = blockIdx.x * blockDim.x + threadIdx.x;
    int e0 = i * 4;
    if (e0 + 3 < N_EDGES) {
        int4 s = *(const int4*)(edge_index + e0);             // src x4
        int4 d = *(const int4*)(edge_index + N_EDGES + e0);   // dst x4
        int p0 = atomicAdd(&g_fill[d.x], 1);
        int p1 = atomicAdd(&g_fill[d.y], 1);
        int p2 = atomicAdd(&g_fill[d.z], 1);
        int p3 = atomicAdd(&g_fill[d.w], 1);
        g_srcs[p0] = s.x;
        g_srcs[p1] = s.y;
        g_srcs[p2] = s.z;
        g_srcs[p3] = s.w;
    } else {
        for (int e = e0; e < N_EDGES; e++) {
            int dst = edge_index[N_EDGES + e];
            int pos = atomicAdd(&g_fill[dst], 1);
            g_srcs[pos] = edge_index[e];
        }
    }
}

// ------- aggregation CH=128 (R7-proven) -------
__global__ void agg128_kernel(const __half* __restrict__ X,
                              const float* __restrict__ eps_ptr,
                              __half* __restrict__ OUT) {
    int gw   = (blockIdx.x * blockDim.x + threadIdx.x) >> 5;
    int lane = threadIdx.x & 31;
    if (gw >= M_PAD) return;
    const bool hi = lane >= 16;
    const int  l4 = lane & 15;
    uint4* orow = (uint4*)(OUT + (size_t)gw * 128);

    if (gw >= N_NODES) {
        if (!hi) orow[l4] = make_uint4(0u, 0u, 0u, 0u);
        return;
    }

    float2 acc[4];
    if (!hi) {
        const float scale = 1.0f + __ldg(eps_ptr);
        uint4 u = __ldg((const uint4*)(X + (size_t)gw * 128) + l4);
        const __half2* hh = (const __half2*)&u;
#pragma unroll
        for (int k = 0; k < 4; k++) {
            float2 f = __half22float2(hh[k]);
            acc[k] = make_float2(f.x * scale, f.y * scale);
        }
    } else {
#pragma unroll
        for (int k = 0; k < 4; k++) acc[k] = make_float2(0.f, 0.f);
    }

    const int beg = g_rowptr[gw];
    const int end = g_rowptr[gw + 1];
    const int sel = hi ? 1 : 0;
    int j = beg;
    for (; j + 3 < end; j += 4) {
        int sA = __ldg(&g_srcs[j + sel]);
        int sB = __ldg(&g_srcs[j + 2 + sel]);
        uint4 uA = __ldg((const uint4*)(X + (size_t)sA * 128) + l4);
        uint4 uB = __ldg((const uint4*)(X + (size_t)sB * 128) + l4);
        const __half2* hA = (const __half2*)&uA;
        const __half2* hB = (const __half2*)&uB;
#pragma unroll
        for (int k = 0; k < 4; k++) {
            float2 f = __half22float2(__hadd2(hA[k], hB[k]));
            acc[k].x += f.x; acc[k].y += f.y;
        }
    }
    if (j + 1 < end) {
        int s = __ldg(&g_srcs[j + sel]);
        uint4 u = __ldg((const uint4*)(X + (size_t)s * 128) + l4);
        const __half2* hh = (const __half2*)&u;
#pragma unroll
        for (int k = 0; k < 4; k++) {
            float2 f = __half22float2(hh[k]);
            acc[k].x += f.x; acc[k].y += f.y;
        }
        j += 2;
    }
    if (j < end && !hi) {
        int s = __ldg(&g_srcs[j]);
        uint4 u = __ldg((const uint4*)(X + (size_t)s * 128) + l4);
        const __half2* hh = (const __half2*)&u;
#pragma unroll
        for (int k = 0; k < 4; k++) {
            float2 f = __half22float2(hh[k]);
            acc[k].x += f.x; acc[k].y += f.y;
        }
    }

#pragma unroll
    for (int k = 0; k < 4; k++) {
        acc[k].x += __shfl_down_sync(0xFFFFFFFF, acc[k].x, 16);
        acc[k].y += __shfl_down_sync(0xFFFFFFFF, acc[k].y, 16);
    }
    if (!hi) {
        uint4 o;
        __half2* oh = (__half2*)&o;
#pragma unroll
        for (int k = 0; k < 4; k++) oh[k] = __floats2half2_rn(acc[k].x, acc[k].y);
        orow[l4] = o;
    }
}

// ------- aggregation CH=256: software-pipelined index loads (isolated change) -------
__global__ void agg256_kernel(const __half* __restrict__ X,
                              const float* __restrict__ eps_ptr,
                              __half* __restrict__ OUT) {
    int gw   = (blockIdx.x * blockDim.x + threadIdx.x) >> 5;
    int lane = threadIdx.x & 31;
    if (gw >= M_PAD) return;

    __half2* orow = (__half2*)(OUT + (size_t)gw * 256) + lane * 4;
    if (gw >= N_NODES) {
        __half2 z = __floats2half2_rn(0.f, 0.f);
#pragma unroll
        for (int v = 0; v < 4; v++) orow[v] = z;
        return;
    }

    const float scale = 1.0f + __ldg(eps_ptr);
    float2 acc[4];
    {
        uint4 u = __ldg((const uint4*)(X + (size_t)gw * 256) + lane);
        const __half2* hh = (const __half2*)&u;
#pragma unroll
        for (int v = 0; v < 4; v++) {
            float2 f = __half22float2(hh[v]);
            acc[v] = make_float2(f.x * scale, f.y * scale);
        }
    }

    const int beg = g_rowptr[gw];
    const int end = g_rowptr[gw + 1];
    int j = beg;

    // pipelined quad loop: prefetch next indices before consuming current rows
    int i0, i1, i2, i3;
    if (j + 3 < end) {
        i0 = __ldg(&g_srcs[j + 0]);
        i1 = __ldg(&g_srcs[j + 1]);
        i2 = __ldg(&g_srcs[j + 2]);
        i3 = __ldg(&g_srcs[j + 3]);
    }
    for (; j + 3 < end; ) {
        const int jn = j + 4;
        int n0, n1, n2, n3;
        if (jn + 3 < end) {
            n0 = __ldg(&g_srcs[jn + 0]);
            n1 = __ldg(&g_srcs[jn + 1]);
            n2 = __ldg(&g_srcs[jn + 2]);
            n3 = __ldg(&g_srcs[jn + 3]);
        }
        uint4 u0 = __ldg((const uint4*)(X + (size_t)i0 * 256) + lane);
        uint4 u1 = __ldg((const uint4*)(X + (size_t)i1 * 256) + lane);
        uint4 u2 = __ldg((const uint4*)(X + (size_t)i2 * 256) + lane);
        uint4 u3 = __ldg((const uint4*)(X + (size_t)i3 * 256) + lane);
        const __half2* h0 = (const __half2*)&u0;
        const __half2* h1 = (const __half2*)&u1;
        const __half2* h2 = (const __half2*)&u2;
        const __half2* h3 = (const __half2*)&u3;
#pragma unroll
        for (int v = 0; v < 4; v++) {
            float2 f0 = __half22float2(__hadd2(h0[v], h1[v]));
            float2 f1 = __half22float2(__hadd2(h2[v], h3[v]));
            acc[v].x += f0.x + f1.x;
            acc[v].y += f0.y + f1.y;
        }
        j = jn;
        i0 = n0; i1 = n1; i2 = n2; i3 = n3;
    }
    if (j + 1 < end) {
        uint4 u0 = __ldg((const uint4*)(X + (size_t)__ldg(&g_srcs[j + 0]) * 256) + lane);
        uint4 u1 = __ldg((const uint4*)(X + (size_t)__ldg(&g_srcs[j + 1]) * 256) + lane);
        const __half2* h0 = (const __half2*)&u0;
        const __half2* h1 = (const __half2*)&u1;
#pragma unroll
        for (int v = 0; v < 4; v++) {
            float2 f0 = __half22float2(__hadd2(h0[v], h1[v]));
            acc[v].x += f0.x; acc[v].y += f0.y;
        }
        j += 2;
    }
    if (j < end) {
        uint4 u0 = __ldg((const uint4*)(X + (size_t)__ldg(&g_srcs[j]) * 256) + lane);
        const __half2* h0 = (const __half2*)&u0;
#pragma unroll
        for (int v = 0; v < 4; v++) {
            float2 f0 = __half22float2(h0[v]);
            acc[v].x += f0.x; acc[v].y += f0.y;
        }
    }

#pragma unroll
    for (int v = 0; v < 4; v++) orow[v] = __floats2half2_rn(acc[v].x, acc[v].y);
}

// ------- fused 2-GEMM MLP (R8/R11-proven): out = actB(relu(A@WaT + ba) @ WbT + bb) -------
template <int K1, int N2, bool OUT_HALF>
__global__ void __launch_bounds__(512, 1)
fused_mlp(const __half* __restrict__ A, const __half* __restrict__ WtA,
          const float* __restrict__ biasA, const __half* __restrict__ WtB,
          const float* __restrict__ biasB, void* __restrict__ outv) {
    constexpr int PITCH  = 80;
    constexpr int A_STG  = 128 * PITCH;          // 10240
    constexpr int B_STG  = 256 * PITCH;          // 20480
    constexpr int STG    = A_STG + B_STG;        // 30720
    constexpr int MID_OFF = 3 * STG;             // 92160
    constexpr int NF2    = N2 / 32;
    extern __shared__ __align__(128) char smem[];
    const uint32_t sbase = smem_u32(smem);

    const int tid  = threadIdx.x;
    const int lane = tid & 31;
    const int wid  = tid >> 5;
    const int wm   = wid & 3;
    const int wn   = wid >> 2;
    const size_t brow = (size_t)blockIdx.x * 128;

    const int g  = lane >> 3;
    const int l7 = lane & 7;
    const uint32_t aRel   = (uint32_t)(wm * 32 + (g & 1) * 8 + l7) * PITCH + (g >> 1) * 16;
    const uint32_t bRelA  = (uint32_t)(wn * 64 + ((g >> 1) & 1) * 8 + l7) * PITCH + (g & 1) * 16;
    const uint32_t bRelB  = (uint32_t)(wn * (N2 / 4) + ((g >> 1) & 1) * 8 + l7) * PITCH + (g & 1) * 16;
    const int lr = lane >> 2;
    const int lc = (lane & 3) * 2;

    float c[2][8][4];
#pragma unroll
    for (int mf = 0; mf < 2; mf++)
#pragma unroll
        for (int nf = 0; nf < 8; nf++)
#pragma unroll
            for (int e = 0; e < 4; e++) c[mf][nf][e] = 0.0f;

    auto load_stageA = [&](int t, int buf) {
        const uint32_t sb = sbase + (uint32_t)buf * STG;
        {
            int row = tid >> 2, cc = tid & 3;
            CP_ASYNC16(sb + row * PITCH + cc * 16, A + (brow + row) * K1 + t * 32 + cc * 8);
        }
#pragma unroll
        for (int p = 1; p < 3; p++) {
            int i2 = tid + p * 512 - 512;
            int row = i2 >> 2, cc = i2 & 3;
            CP_ASYNC16(sb + A_STG + row * PITCH + cc * 16,
                       WtA + (size_t)row * K1 + t * 32 + cc * 8);
        }
    };
    auto load_stageB = [&](int t, int buf) {
        const uint32_t sb = sbase + (uint32_t)buf * STG + A_STG;
#pragma unroll
        for (int p = 0; p < (N2 * 4) / 512; p++) {
            int idx = tid + p * 512;
            int row = idx >> 2, cc = idx & 3;
            CP_ASYNC16(sb + row * PITCH + cc * 16,
                       WtB + (size_t)row * 256 + t * 32 + cc * 8);
        }
    };

    // ================= phase A mainloop =================
    constexpr int T1 = K1 / 32;
    load_stageA(0, 0); CP_COMMIT();
    load_stageA(1, 1); CP_COMMIT();
    int buf = 0;
    for (int t = 0; t < T1; t++) {
        CP_WAIT(1);
        __syncthreads();
        if (t + 2 < T1) load_stageA(t + 2, (t + 2) % 3);
        CP_COMMIT();
        const uint32_t soff = (uint32_t)buf * STG;
#pragma unroll
        for (int ks = 0; ks < 2; ks++) {
            uint32_t a[2][4], b[8][2];
            ldsm4(a[0], sbase + soff + aRel + ks * 32);
            ldsm4(a[1], sbase + soff + aRel + 16 * PITCH + ks * 32);
#pragma unroll
            for (int p = 0; p < 4; p++) {
                uint32_t r[4];
                ldsm4(r, sbase + soff + A_STG + bRelA + p * 16 * PITCH + ks * 32);
                b[2 * p][0] = r[0]; b[2 * p][1] = r[1];
                b[2 * p + 1][0] = r[2]; b[2 * p + 1][1] = r[3];
            }
#pragma unroll
            for (int mf = 0; mf < 2; mf++)
#pragma unroll
                for (int nf = 0; nf < 8; nf++)
                    mma16816(c[mf][nf], a[mf], b[nf]);
        }
        buf = (buf == 2) ? 0 : buf + 1;
    }
    __syncthreads();

    // prefetch phase-B stages while epilogue A runs
    load_stageB(0, 0); CP_COMMIT();
    load_stageB(1, 1); CP_COMMIT();

    // ---- phase A epilogue -> mid tile in SMEM (fp16, slab layout) ----
#pragma unroll
    for (int nf = 0; nf < 8; nf++) {
        const int col0 = wn * 64 + nf * 8 + lc;
        float2 bv = *(const float2*)(biasA + col0);
        const int slab = col0 >> 5, cin = col0 & 31;
        const uint32_t mb = sbase + MID_OFF + slab * A_STG + cin * 2;
#pragma unroll
        for (int mf = 0; mf < 2; mf++) {
            const int row0 = wm * 32 + mf * 16 + lr;
            float v0 = fmaxf(c[mf][nf][0] + bv.x, 0.f);
            float v1 = fmaxf(c[mf][nf][1] + bv.y, 0.f);
            float v2 = fmaxf(c[mf][nf][2] + bv.x, 0.f);
            float v3 = fmaxf(c[mf][nf][3] + bv.y, 0.f);
            __half2 h0 = __floats2half2_rn(v0, v1);
            __half2 h1 = __floats2half2_rn(v2, v3);
            asm volatile("st.shared.b32 [%0], %1;" :: "r"(mb + row0 * PITCH), "r"(*(uint32_t*)&h0));
            asm volatile("st.shared.b32 [%0], %1;" :: "r"(mb + (row0 + 8) * PITCH), "r"(*(uint32_t*)&h1));
        }
    }
#pragma unroll
    for (int mf = 0; mf < 2; mf++)
#pragma unroll
        for (int nf = 0; nf < 8; nf++)
#pragma unroll
            for (int e = 0; e < 4; e++) c[mf][nf][e] = 0.0f;
    __syncthreads();

    // ================= phase B mainloop (K2 = 256) =================
    buf = 0;
    for (int t = 0; t < 8; t++) {
        CP_WAIT(1);
        __syncthreads();
        if (t + 2 < 8) load_stageB(t + 2, (t + 2) % 3);
        CP_COMMIT();
        const uint32_t soff = (uint32_t)buf * STG + A_STG;
        const uint32_t amid = sbase + MID_OFF + (uint32_t)t * A_STG;
#pragma unroll
        for (int ks = 0; ks < 2; ks++) {
            uint32_t a[2][4], b[8][2];
            ldsm4(a[0], amid + aRel + ks * 32);
            ldsm4(a[1], amid + aRel + 16 * PITCH + ks * 32);
#pragma unroll
            for (int p = 0; p < NF2 / 2; p++) {
                uint32_t r[4];
                ldsm4(r, sbase + soff + bRelB + p * 16 * PITCH + ks * 32);
                b[2 * p][0] = r[0]; b[2 * p][1] = r[1];
                b[2 * p + 1][0] = r[2]; b[2 * p + 1][1] = r[3];
            }
#pragma unroll
            for (int mf = 0; mf < 2; mf++)
#pragma unroll
                for (int nf = 0; nf < NF2; nf++)
                    mma16816(c[mf][nf], a[mf], b[nf]);
        }
        buf = (buf == 2) ? 0 : buf + 1;
    }

    // ---- phase B epilogue ----
#pragma unroll
    for (int nf = 0; nf < NF2; nf++) {
        const int col = wn * (N2 / 4) + nf * 8 + lc;
        float2 bv = *(const float2*)(biasB + col);
#pragma unroll
        for (int mf = 0; mf < 2; mf++) {
            size_t r0 = brow + wm * 32 + mf * 16 + lr;
            float v0 = c[mf][nf][0] + bv.x, v1 = c[mf][nf][1] + bv.y;
            float v2 = c[mf][nf][2] + bv.x, v3 = c[mf][nf][3] + bv.y;
            if (OUT_HALF) {
                v0 = fmaxf(v0, 0.f); v1 = fmaxf(v1, 0.f);
                v2 = fmaxf(v2, 0.f); v3 = fmaxf(v3, 0.f);
                __half* C = (__half*)outv;
                *(__half2*)(C + r0 * N2 + col)       = __floats2half2_rn(v0, v1);
                *(__half2*)(C + (r0 + 8) * N2 + col) = __floats2half2_rn(v2, v3);
            } else {
                float* C = (float*)outv;
                if (r0 < N_NODES)     *(float2*)(C + r0 * N2 + col)       = make_float2(v0, v1);
                if (r0 + 8 < N_NODES) *(float2*)(C + (r0 + 8) * N2 + col) = make_float2(v2, v3);
            }
        }
    }
}

// ---------------- launch ----------------
extern "C" void kernel_launch(void* const* d_in, const int* in_sizes, int n_in,
                              void* d_out, int out_size) {
    const float* x    = (const float*)d_in[0];
    const int*   ei   = (const int*)  d_in[1];
    const float* eps1 = (const float*)d_in[2];
    const float* W1a  = (const float*)d_in[3];
    const float* b1a  = (const float*)d_in[4];
    const float* W1b  = (const float*)d_in[5];
    const float* b1b  = (const float*)d_in[6];
    const float* eps2 = (const float*)d_in[7];
    const float* W2a  = (const float*)d_in[8];
    const float* b2a  = (const float*)d_in[9];
    const float* W2b  = (const float*)d_in[10];
    const float* b2b  = (const float*)d_in[11];
    float* out = (float*)d_out;

    __half *xh, *bufA, *h, *wt;
    cudaGetSymbolAddress((void**)&xh,   g_xh);
    cudaGetSymbolAddress((void**)&bufA, g_bufA);
    cudaGetSymbolAddress((void**)&h,    g_h);
    cudaGetSymbolAddress((void**)&wt,   g_wt);
    __half* wt1a = wt;               // [256][128]
    __half* wt1b = wt + 32768;       // [256][256]
    __half* wt2a = wt + 98304;       // [256][256]
    __half* wt2b = wt + 163840;      // [128][256]

    constexpr int SMEM_MLP = 3 * 30720 + 8 * 10240;   // 174080
    cudaFuncSetAttribute((const void*)fused_mlp<128, 256, true>,
                         cudaFuncAttributeMaxDynamicSharedMemorySize, SMEM_MLP);
    cudaFuncSetAttribute((const void*)fused_mlp<256, 128, false>,
                         cudaFuncAttributeMaxDynamicSharedMemorySize, SMEM_MLP);

    const int agg_blocks = (M_PAD * 32 + 255) / 256;
    const int G = M_PAD / 128;  // 782

    hist_cvt_kernel<<<(N_EDGES / 4 + 255) / 256, 256>>>(ei, x);                  // 1
    scan1_tr_kernel<<<SCAN_BLOCKS + TR_BLOCKS, 1024>>>(W1a, W1b, W2a, W2b, wt);  // 2
    scan2_kernel<<<SCAN_BLOCKS, 1024>>>();                                       // 3
    scatter_kernel<<<(N_EDGES / 4 + 255) / 256, 256>>>(ei);                      // 4 (profiled)

    // ---- layer 1 ----
    agg128_kernel<<<agg_blocks, 256>>>(xh, eps1, bufA);                          // 5
    fused_mlp<128, 256, true><<<G, 512, SMEM_MLP>>>(bufA, wt1a, b1a, wt1b, b1b, h);

    // ---- layer 2 ----
    agg256_kernel<<<agg_blocks, 256>>>(h, eps2, bufA);
    fused_mlp<256, 128, false><<<G, 512, SMEM_MLP>>>(bufA, wt2a, b2a, wt2b, b2b, out);
}